// round 1
// baseline (speedup 1.0000x reference)
#include <cuda_runtime.h>
#include <math.h>

#define Nn 512
#define CS 1024
#define CZ 128
#define Hh 12
#define HD 16
#define PQ 4
#define PV 8
#define CATD 2112   // 192 + 96*4 + 1536
#define NN (Nn*Nn)

// ---------------- scratch (device globals; no allocation) ----------------
__device__ float g_q[Nn*Hh*HD];            // [n][h][d]  (raw proj layout)
__device__ float g_kv[Nn*Hh*2*HD];         // [n][h][2*HD]  k=:16, v=16:
__device__ float g_qp_raw[Nn*Hh*PQ*3];     // raw s@Wqp (N,144)
__device__ float g_kvp_raw[Nn*Hh*(PQ+PV)*3]; // raw s@Wkvp (N,432)
__device__ float g_qpts[Nn*Hh*PQ*3];       // [n][h][p][c]
__device__ float g_kpts[Nn*Hh*PQ*3];
__device__ float g_vpts[Nn*Hh*PV*3];
__device__ float g_bias[Hh*NN];            // [h][i][j]
__device__ float g_att[Hh*NN];             // softmaxed attention
__device__ float g_cat[Nn*CATD];

// ---------------- generic tiled GEMM: C[M,Nd] = A[M,K] @ W[K,Nd] + bias ---
__global__ void gemm_bias_kernel(const float* __restrict__ A,
                                 const float* __restrict__ W,
                                 const float* __restrict__ bias,
                                 float* __restrict__ C,
                                 int M, int Nd, int K) {
    __shared__ float As[16][64];
    __shared__ float Bs[16][64 + 4];
    int tid = threadIdx.x;
    int tx = tid % 16, ty = tid / 16;
    int row0 = blockIdx.y * 64 + ty * 4;
    int col0 = blockIdx.x * 64 + tx * 4;
    float acc[4][4] = {};
    for (int k0 = 0; k0 < K; k0 += 16) {
        for (int t = tid; t < 64 * 16; t += 256) {
            int r = t >> 4, kk = t & 15;
            int gr = blockIdx.y * 64 + r;
            As[kk][r] = (gr < M) ? A[gr * K + k0 + kk] : 0.f;
        }
        for (int t = tid; t < 16 * 64; t += 256) {
            int kk = t >> 6, c = t & 63;
            int gc = blockIdx.x * 64 + c;
            Bs[kk][c] = (gc < Nd) ? W[(k0 + kk) * Nd + gc] : 0.f;
        }
        __syncthreads();
        #pragma unroll
        for (int kk = 0; kk < 16; kk++) {
            float a[4], b[4];
            #pragma unroll
            for (int i = 0; i < 4; i++) a[i] = As[kk][ty * 4 + i];
            #pragma unroll
            for (int j = 0; j < 4; j++) b[j] = Bs[kk][tx * 4 + j];
            #pragma unroll
            for (int i = 0; i < 4; i++)
                #pragma unroll
                for (int j = 0; j < 4; j++) acc[i][j] += a[i] * b[j];
        }
        __syncthreads();
    }
    #pragma unroll
    for (int i = 0; i < 4; i++) {
        int r = row0 + i;
        if (r >= M) continue;
        #pragma unroll
        for (int j = 0; j < 4; j++) {
            int c = col0 + j;
            if (c >= Nd) continue;
            C[r * Nd + c] = acc[i][j] + bias[c];
        }
    }
}

// ------------- point transforms: rotate+translate raw projections ---------
// q_pts: raw (N,144) split3 -> (N,48,3), pts = R p + t
__global__ void qpts_kernel(const float* __restrict__ rot,
                            const float* __restrict__ trans) {
    int n = blockIdx.x;
    __shared__ float R[9], t3[3];
    if (threadIdx.x < 9) R[threadIdx.x] = rot[n * 9 + threadIdx.x];
    if (threadIdx.x < 3) t3[threadIdx.x] = trans[n * 3 + threadIdx.x];
    __syncthreads();
    int idx = threadIdx.x;          // h*4 + p, 0..47
    if (idx < 48) {
        float p0 = g_qp_raw[n * 144 + idx];
        float p1 = g_qp_raw[n * 144 + 48 + idx];
        float p2 = g_qp_raw[n * 144 + 96 + idx];
        #pragma unroll
        for (int c = 0; c < 3; c++) {
            float o = R[c * 3] * p0 + R[c * 3 + 1] * p1 + R[c * 3 + 2] * p2 + t3[c];
            g_qpts[n * 144 + idx * 3 + c] = o;
        }
    }
}

// kv_pts: raw (N,432) split3 -> (N,144,3); first 4 per head -> k_pts, last 8 -> v_pts
__global__ void kvpts_kernel(const float* __restrict__ rot,
                             const float* __restrict__ trans) {
    int n = blockIdx.x;
    __shared__ float R[9], t3[3];
    if (threadIdx.x < 9) R[threadIdx.x] = rot[n * 9 + threadIdx.x];
    if (threadIdx.x < 3) t3[threadIdx.x] = trans[n * 3 + threadIdx.x];
    __syncthreads();
    int idx = threadIdx.x;          // h*12 + r, 0..143
    if (idx < 144) {
        float p0 = g_kvp_raw[n * 432 + idx];
        float p1 = g_kvp_raw[n * 432 + 144 + idx];
        float p2 = g_kvp_raw[n * 432 + 288 + idx];
        int h = idx / 12, r = idx % 12;
        float o[3];
        #pragma unroll
        for (int c = 0; c < 3; c++)
            o[c] = R[c * 3] * p0 + R[c * 3 + 1] * p1 + R[c * 3 + 2] * p2 + t3[c];
        if (r < PQ) {
            #pragma unroll
            for (int c = 0; c < 3; c++)
                g_kpts[n * 144 + h * 12 + r * 3 + c] = o[c];
        } else {
            int p = r - PQ;
            #pragma unroll
            for (int c = 0; c < 3; c++)
                g_vpts[n * 288 + h * 24 + p * 3 + c] = o[c];
        }
    }
}

// ---------- bias: b[h][i][j] = z[i,j,:] @ Wb[:,h] + bb[h] -----------------
__global__ void bias_kernel(const float* __restrict__ z,
                            const float* __restrict__ Wb,
                            const float* __restrict__ bb) {
    int base = blockIdx.x * 8;   // 8 flattened (i,j) rows per block
    __shared__ float zs[8][CZ];
    __shared__ float Wbs[CZ * Hh];
    int tid = threadIdx.x;       // 128
    for (int t = tid; t < CZ * Hh; t += 128) Wbs[t] = Wb[t];
    #pragma unroll
    for (int r = 0; r < 8; r++)
        zs[r][tid] = z[(size_t)(base + r) * CZ + tid];
    __syncthreads();
    if (tid < 96) {
        int r = tid / 12, h = tid % 12;
        float acc = bb[h];
        #pragma unroll 8
        for (int c = 0; c < CZ; c++) acc += zs[r][c] * Wbs[c * Hh + h];
        int ij = base + r;
        int i = ij >> 9, j = ij & 511;
        g_bias[h * NN + i * Nn + j] = acc;
    }
}

// ---------- attention logits + softmax per (h, i) row ---------------------
__global__ void attn_kernel(const float* __restrict__ head_w,
                            const float* __restrict__ mask) {
    int h = blockIdx.x, i = blockIdx.y;
    __shared__ float qv[16], qp[12];
    __shared__ float red[256];
    __shared__ float s_hw, s_mi;
    int tid = threadIdx.x;   // 256
    if (tid < 16) qv[tid] = g_q[i * 192 + h * 16 + tid];
    if (tid < 12) qp[tid] = g_qpts[i * 144 + h * 12 + tid];
    if (tid == 0) {
        float w = head_w[h];
        float sp = (w > 0.f) ? (w + log1pf(expf(-w))) : log1pf(expf(w));
        s_hw = sp * 0.13608276348795434f;   // sqrt(1/54)
        s_mi = mask[i];
    }
    __syncthreads();
    float logit[2];
    #pragma unroll
    for (int jj = 0; jj < 2; jj++) {
        int j = tid + jj * 256;
        const float* kptr = g_kv + j * 384 + h * 32;
        float dot = 0.f;
        #pragma unroll
        for (int d = 0; d < 16; d++) dot += qv[d] * kptr[d];
        const float* kp = g_kpts + j * 144 + h * 12;
        float pts = 0.f;
        #pragma unroll
        for (int e = 0; e < 12; e++) { float dd = qp[e] - kp[e]; pts += dd * dd; }
        logit[jj] = dot * 0.14433756729740643f                // sqrt(1/48)
                  + 0.5773502691896258f * g_bias[(h << 18) + (i << 9) + j]
                  - 0.5f * s_hw * pts
                  + 100000.0f * (s_mi * mask[j] - 1.0f);
    }
    // row max
    float m = fmaxf(logit[0], logit[1]);
    red[tid] = m; __syncthreads();
    for (int s = 128; s > 0; s >>= 1) {
        if (tid < s) red[tid] = fmaxf(red[tid], red[tid + s]);
        __syncthreads();
    }
    m = red[0]; __syncthreads();
    float e0 = expf(logit[0] - m), e1 = expf(logit[1] - m);
    red[tid] = e0 + e1; __syncthreads();
    for (int s = 128; s > 0; s >>= 1) {
        if (tid < s) red[tid] += red[tid + s];
        __syncthreads();
    }
    float inv = 1.f / red[0];
    g_att[(h << 18) + (i << 9) + tid] = e0 * inv;
    g_att[(h << 18) + (i << 9) + tid + 256] = e1 * inv;
}

// ---------- o = a@v, o_pt = a@v_pts, inverse-frame transform + norm -------
__global__ void out_kernel(const float* __restrict__ rot,
                           const float* __restrict__ trans) {
    int h = blockIdx.x, i = blockIdx.y;
    __shared__ float as[Nn];
    __shared__ float opt[24];
    __shared__ float R[9], t3[3];
    int tid = threadIdx.x;   // 64
    for (int j = tid; j < Nn; j += 64) as[j] = g_att[(h << 18) + (i << 9) + j];
    if (tid < 9) R[tid] = rot[i * 9 + tid];
    if (tid < 3) t3[tid] = trans[i * 3 + tid];
    __syncthreads();
    if (tid < 16) {
        float acc = 0.f;
        #pragma unroll 8
        for (int j = 0; j < Nn; j++) acc += as[j] * g_kv[j * 384 + h * 32 + 16 + tid];
        g_cat[i * CATD + h * 16 + tid] = acc;
    } else if (tid < 40) {
        int pp = tid - 16;
        float acc = 0.f;
        #pragma unroll 8
        for (int j = 0; j < Nn; j++) acc += as[j] * g_vpts[j * 288 + h * 24 + pp];
        opt[pp] = acc;
    }
    __syncthreads();
    if (tid < 8) {
        int p = tid;
        float x = opt[p * 3 + 0] - t3[0];
        float y = opt[p * 3 + 1] - t3[1];
        float z = opt[p * 3 + 2] - t3[2];
        float lx = R[0] * x + R[3] * y + R[6] * z;   // R^T
        float ly = R[1] * x + R[4] * y + R[7] * z;
        float lz = R[2] * x + R[5] * y + R[8] * z;
        int o = i * CATD;
        g_cat[o + 192 + h * 8 + p] = lx;
        g_cat[o + 288 + h * 8 + p] = ly;
        g_cat[o + 384 + h * 8 + p] = lz;
        g_cat[o + 480 + h * 8 + p] = sqrtf(lx * lx + ly * ly + lz * lz + 1e-8f);
    }
}

// ---------- o_pair: cat[i, 576 + h*128 + c] = sum_j a[h,i,j] z[i,j,c] -----
__global__ void opair_kernel(const float* __restrict__ z) {
    int i = blockIdx.x;
    __shared__ float as[Hh][Nn];   // 24 KB
    int tid = threadIdx.x;   // 128 (= channel c)
    for (int t = tid; t < Hh * Nn; t += 128) {
        int h = t >> 9, j = t & 511;
        as[h][j] = g_att[(h << 18) + (i << 9) + j];
    }
    __syncthreads();
    float acc[Hh];
    #pragma unroll
    for (int h = 0; h < Hh; h++) acc[h] = 0.f;
    const float* zrow = z + (size_t)i * Nn * CZ + tid;
    #pragma unroll 4
    for (int j = 0; j < Nn; j++) {
        float zv = zrow[j * CZ];
        #pragma unroll
        for (int h = 0; h < Hh; h++) acc[h] += as[h][j] * zv;
    }
    int o = i * CATD + 576;
    #pragma unroll
    for (int h = 0; h < Hh; h++) g_cat[o + h * CZ + tid] = acc[h];
}

// --------------------------------------------------------------------------
extern "C" void kernel_launch(void* const* d_in, const int* in_sizes, int n_in,
                              void* d_out, int out_size) {
    const float* s      = (const float*)d_in[0];
    const float* z      = (const float*)d_in[1];
    const float* rot    = (const float*)d_in[2];
    const float* trans  = (const float*)d_in[3];
    const float* mask   = (const float*)d_in[4];
    const float* Wq     = (const float*)d_in[5];
    const float* bq     = (const float*)d_in[6];
    const float* Wkv    = (const float*)d_in[7];
    const float* bkv    = (const float*)d_in[8];
    const float* Wqp    = (const float*)d_in[9];
    const float* bqp    = (const float*)d_in[10];
    const float* Wkvp   = (const float*)d_in[11];
    const float* bkvp   = (const float*)d_in[12];
    const float* Wb     = (const float*)d_in[13];
    const float* bb     = (const float*)d_in[14];
    const float* head_w = (const float*)d_in[15];
    const float* Wout   = (const float*)d_in[16];
    const float* bout   = (const float*)d_in[17];
    float* out = (float*)d_out;

    float *p_q, *p_kv, *p_qpr, *p_kvpr, *p_cat;
    cudaGetSymbolAddress((void**)&p_q,    g_q);
    cudaGetSymbolAddress((void**)&p_kv,   g_kv);
    cudaGetSymbolAddress((void**)&p_qpr,  g_qp_raw);
    cudaGetSymbolAddress((void**)&p_kvpr, g_kvp_raw);
    cudaGetSymbolAddress((void**)&p_cat,  g_cat);

    // projections
    gemm_bias_kernel<<<dim3(3, 8), 256>>>(s, Wq,   bq,   p_q,    Nn, 192, CS);
    gemm_bias_kernel<<<dim3(6, 8), 256>>>(s, Wkv,  bkv,  p_kv,   Nn, 384, CS);
    gemm_bias_kernel<<<dim3(3, 8), 256>>>(s, Wqp,  bqp,  p_qpr,  Nn, 144, CS);
    gemm_bias_kernel<<<dim3(7, 8), 256>>>(s, Wkvp, bkvp, p_kvpr, Nn, 432, CS);
    // rigid transforms of points
    qpts_kernel<<<Nn, 64>>>(rot, trans);
    kvpts_kernel<<<Nn, 160>>>(rot, trans);
    // pair bias
    bias_kernel<<<NN / 8, 128>>>(z, Wb, bb);
    // attention (logits + pt-att + mask + softmax)
    attn_kernel<<<dim3(Hh, Nn), 256>>>(head_w, mask);
    // scalar + point outputs
    out_kernel<<<dim3(Hh, Nn), 64>>>(rot, trans);
    // pair output
    opair_kernel<<<Nn, 128>>>(z);
    // final projection
    gemm_bias_kernel<<<dim3(16, 8), 256>>>(p_cat, Wout, bout, out, Nn, CS, CATD);
}

// round 2
// speedup vs baseline: 2.3517x; 2.3517x over previous
#include <cuda_runtime.h>
#include <math.h>

#define Nn 512
#define CS 1024
#define CZ 128
#define Hh 12
#define HD 16
#define PQ 4
#define PV 8
#define CATD 2112   // 192 + 96*4 + 1536
#define NN (Nn*Nn)
#define PROJD 1152  // 192 + 384 + 144 + 432

// ---------------- scratch (device globals; no allocation) ----------------
__device__ float g_Wcat[CS*PROJD];        // packed Wq|Wkv|Wqp|Wkvp
__device__ float g_bcat[PROJD];
__device__ float g_proj[Nn*PROJD];        // [n][ q(192) | kv(384) | qp_raw(144) | kvp_raw(432) ]
__device__ float g_qpts[Nn*Hh*PQ*3];      // [n][h][p][c]
__device__ float g_kpts[Nn*Hh*PQ*3];
__device__ float g_vpts[Nn*Hh*PV*3];
__device__ float g_bias[Hh*NN];           // [h][i][j], pre-scaled by sqrt(1/3)
__device__ float g_att[Hh*NN];            // softmaxed attention
__device__ float g_opt[Nn*Hh*PV*3];       // global-frame o_pt before inverse transform
__device__ float g_cat[Nn*CATD];

// ---------------- pack weights: W* -> g_Wcat, b* -> g_bcat ----------------
__global__ void packW_kernel(const float* __restrict__ Wq,  const float* __restrict__ bq,
                             const float* __restrict__ Wkv, const float* __restrict__ bkv,
                             const float* __restrict__ Wqp, const float* __restrict__ bqp,
                             const float* __restrict__ Wkvp,const float* __restrict__ bkvp) {
    const float QS = 0.14433756729740643f;  // sqrt(1/48) folded into q proj
    int idx = blockIdx.x * 256 + threadIdx.x;
    const int total = CS * PROJD;
    if (idx < total) {
        int row = idx / PROJD, col = idx - row * PROJD;
        float v;
        if      (col < 192) v = Wq  [row * 192 + col]         * QS;
        else if (col < 576) v = Wkv [row * 384 + col - 192];
        else if (col < 720) v = Wqp [row * 144 + col - 576];
        else                v = Wkvp[row * 432 + col - 720];
        g_Wcat[idx] = v;
    } else if (idx < total + PROJD) {
        int col = idx - total;
        float v;
        if      (col < 192) v = bq  [col]       * QS;
        else if (col < 576) v = bkv [col - 192];
        else if (col < 720) v = bqp [col - 576];
        else                v = bkvp[col - 720];
        g_bcat[col] = v;
    }
}

// ---------------- GEMM: C[M,Nd] = A[M,K]@W[K,Nd] + bias ------------------
// BM=128, BN=32, BK=16, 128 threads, 8x4 micro-tile, register prefetch.
// Requires: M%128==0, Nd%32==0, K%16==0 (all call sites satisfy this).
__global__ void __launch_bounds__(128)
gemm128_kernel(const float* __restrict__ A,
               const float* __restrict__ W,
               const float* __restrict__ bias,
               float* __restrict__ C,
               int Nd, int K) {
    __shared__ float As[16][128];
    __shared__ float Bs[16][32];
    int tid = threadIdx.x;
    int m0 = blockIdx.y * 128, n0 = blockIdx.x * 32;
    int tx = tid & 7, ty = tid >> 3;

    const float* Arow = A + (size_t)(m0 + tid) * K;
    const float* Bptr = W + (size_t)(tid >> 3) * Nd + n0 + (tid & 7) * 4;

    float4 a4[4], b4;
    #pragma unroll
    for (int u = 0; u < 4; u++) a4[u] = *(const float4*)(Arow + u * 4);
    b4 = *(const float4*)(Bptr);

    float acc[8][4] = {};
    int KT = K >> 4;
    for (int kt = 0; kt < KT; kt++) {
        __syncthreads();
        #pragma unroll
        for (int u = 0; u < 4; u++) {
            As[u * 4 + 0][tid] = a4[u].x;
            As[u * 4 + 1][tid] = a4[u].y;
            As[u * 4 + 2][tid] = a4[u].z;
            As[u * 4 + 3][tid] = a4[u].w;
        }
        *(float4*)&Bs[tid >> 3][(tid & 7) * 4] = b4;
        __syncthreads();
        if (kt + 1 < KT) {
            const float* An = Arow + (kt + 1) * 16;
            #pragma unroll
            for (int u = 0; u < 4; u++) a4[u] = *(const float4*)(An + u * 4);
            b4 = *(const float4*)(Bptr + (size_t)(kt + 1) * 16 * Nd);
        }
        #pragma unroll
        for (int kk = 0; kk < 16; kk++) {
            float4 b  = *(const float4*)&Bs[kk][tx * 4];
            float4 x0 = *(const float4*)&As[kk][ty * 8];
            float4 x1 = *(const float4*)&As[kk][ty * 8 + 4];
            float am[8] = {x0.x, x0.y, x0.z, x0.w, x1.x, x1.y, x1.z, x1.w};
            #pragma unroll
            for (int r = 0; r < 8; r++) {
                acc[r][0] += am[r] * b.x;
                acc[r][1] += am[r] * b.y;
                acc[r][2] += am[r] * b.z;
                acc[r][3] += am[r] * b.w;
            }
        }
    }
    float4 bv = *(const float4*)(bias + n0 + tx * 4);
    #pragma unroll
    for (int r = 0; r < 8; r++) {
        float4 o;
        o.x = acc[r][0] + bv.x; o.y = acc[r][1] + bv.y;
        o.z = acc[r][2] + bv.z; o.w = acc[r][3] + bv.w;
        *(float4*)(C + (size_t)(m0 + ty * 8 + r) * Nd + n0 + tx * 4) = o;
    }
}

// ------------- point transforms (fused q_pts + kv_pts) --------------------
__global__ void pts_kernel(const float* __restrict__ rot,
                           const float* __restrict__ trans) {
    int n = blockIdx.x;
    __shared__ float R[9], t3[3];
    int tid = threadIdx.x;   // 192
    if (tid < 9) R[tid] = rot[n * 9 + tid];
    if (tid < 3) t3[tid] = trans[n * 3 + tid];
    __syncthreads();
    if (tid < 48) {
        int idx = tid;   // h*4 + p
        const float* raw = g_proj + n * PROJD + 576;
        float p0 = raw[idx], p1 = raw[48 + idx], p2 = raw[96 + idx];
        #pragma unroll
        for (int c = 0; c < 3; c++)
            g_qpts[n * 144 + idx * 3 + c] =
                R[c * 3] * p0 + R[c * 3 + 1] * p1 + R[c * 3 + 2] * p2 + t3[c];
    } else {
        int idx = tid - 48;  // h*12 + r, 0..143
        const float* raw = g_proj + n * PROJD + 720;
        float p0 = raw[idx], p1 = raw[144 + idx], p2 = raw[288 + idx];
        int h = idx / 12, r = idx - h * 12;
        float o[3];
        #pragma unroll
        for (int c = 0; c < 3; c++)
            o[c] = R[c * 3] * p0 + R[c * 3 + 1] * p1 + R[c * 3 + 2] * p2 + t3[c];
        if (r < PQ) {
            #pragma unroll
            for (int c = 0; c < 3; c++) g_kpts[n * 144 + h * 12 + r * 3 + c] = o[c];
        } else {
            int p = r - PQ;
            #pragma unroll
            for (int c = 0; c < 3; c++) g_vpts[n * 288 + h * 24 + p * 3 + c] = o[c];
        }
    }
}

// ---------- bias: b[h][i][j] = sqrt(1/3) * (z[i,j,:]@Wb[:,h] + bb[h]) -----
__global__ void bias_kernel(const float* __restrict__ z,
                            const float* __restrict__ Wb,
                            const float* __restrict__ bb) {
    int base = blockIdx.x * 8;
    __shared__ float zs[8][CZ];
    __shared__ float Wbs[CZ * Hh];
    int tid = threadIdx.x;   // 128
    for (int t = tid; t < CZ * Hh; t += 128) Wbs[t] = Wb[t];
    #pragma unroll
    for (int r = 0; r < 8; r++)
        zs[r][tid] = z[(size_t)(base + r) * CZ + tid];
    __syncthreads();
    if (tid < 96) {
        int r = tid / 12, h = tid - r * 12;
        float acc = bb[h];
        #pragma unroll 8
        for (int c = 0; c < CZ; c++) acc += zs[r][c] * Wbs[c * Hh + h];
        int ij = base + r;
        int i = ij >> 9, j = ij & 511;
        g_bias[h * NN + i * Nn + j] = 0.5773502691896258f * acc;
    }
}

// ---------- attention logits + softmax per (h, i) row ---------------------
__global__ void attn_kernel(const float* __restrict__ head_w,
                            const float* __restrict__ mask) {
    int h = blockIdx.x, i = blockIdx.y;
    __shared__ float qv[16], qp[12];
    __shared__ float red8[8];
    __shared__ float s_hw, s_mi, s_b;
    int tid = threadIdx.x;   // 256
    int lane = tid & 31, wid = tid >> 5;
    if (tid < 16) qv[tid] = g_proj[i * PROJD + h * 16 + tid];   // pre-scaled
    if (tid < 12) qp[tid] = g_qpts[i * 144 + h * 12 + tid];
    if (tid == 0) {
        float w = head_w[h];
        float sp = fmaxf(w, 0.f) + log1pf(__expf(-fabsf(w)));
        s_hw = sp * 0.13608276348795434f;   // sqrt(1/54)
        s_mi = mask[i];
    }
    __syncthreads();
    float logit[2];
    #pragma unroll
    for (int jj = 0; jj < 2; jj++) {
        int j = tid + jj * 256;
        const float* kptr = g_proj + j * PROJD + 192 + h * 32;
        float dot = 0.f;
        #pragma unroll
        for (int d = 0; d < 16; d++) dot += qv[d] * kptr[d];
        const float* kp = g_kpts + j * 144 + h * 12;
        float pts = 0.f;
        #pragma unroll
        for (int e = 0; e < 12; e++) { float dd = qp[e] - kp[e]; pts += dd * dd; }
        logit[jj] = dot + g_bias[(h << 18) + (i << 9) + j]
                  - 0.5f * s_hw * pts
                  + 100000.0f * (s_mi * mask[j] - 1.0f);
    }
    // block max via shuffles
    float m = fmaxf(logit[0], logit[1]);
    #pragma unroll
    for (int o = 16; o > 0; o >>= 1) m = fmaxf(m, __shfl_xor_sync(0xffffffffu, m, o));
    if (lane == 0) red8[wid] = m;
    __syncthreads();
    if (tid == 0) {
        float mm = red8[0];
        #pragma unroll
        for (int w = 1; w < 8; w++) mm = fmaxf(mm, red8[w]);
        s_b = mm;
    }
    __syncthreads();
    m = s_b;
    float e0 = __expf(logit[0] - m), e1 = __expf(logit[1] - m);
    float ss = e0 + e1;
    #pragma unroll
    for (int o = 16; o > 0; o >>= 1) ss += __shfl_xor_sync(0xffffffffu, ss, o);
    __syncthreads();
    if (lane == 0) red8[wid] = ss;
    __syncthreads();
    if (tid == 0) {
        float t = 0.f;
        #pragma unroll
        for (int w = 0; w < 8; w++) t += red8[w];
        s_b = 1.f / t;
    }
    __syncthreads();
    float inv = s_b;
    g_att[(h << 18) + (i << 9) + tid]       = e0 * inv;
    g_att[(h << 18) + (i << 9) + tid + 256] = e1 * inv;
}

// ---------- a@[v | v_pts] per head as batched GEMM ------------------------
// grid (12, 8), block 320: tile 64 rows(i) x 40 cols (16 v + 24 vpts), K=512
__global__ void __launch_bounds__(320)
av_kernel() {
    int h = blockIdx.x;
    int i0 = blockIdx.y * 64;
    __shared__ float As[32][64];
    __shared__ float Vt[32][40];
    int tid = threadIdx.x;
    int tx = tid % 40, ty = tid / 40;   // ty 0..7
    float acc[8] = {};
    for (int k0 = 0; k0 < Nn; k0 += 32) {
        __syncthreads();
        for (int t = tid; t < 2048; t += 320) {
            int ii = t & 63, j = t >> 6;
            As[j][ii] = g_att[(h << 18) + ((i0 + ii) << 9) + k0 + j];
        }
        for (int t = tid; t < 1280; t += 320) {
            int col = t % 40, row = t / 40;
            float v;
            if (col < 16) v = g_proj[(size_t)(k0 + row) * PROJD + 192 + h * 32 + 16 + col];
            else          v = g_vpts[(k0 + row) * 288 + h * 24 + (col - 16)];
            Vt[row][col] = v;
        }
        __syncthreads();
        #pragma unroll
        for (int j = 0; j < 32; j++) {
            float b = Vt[j][tx];
            float4 a0 = *(const float4*)&As[j][ty * 8];
            float4 a1 = *(const float4*)&As[j][ty * 8 + 4];
            acc[0] += a0.x * b; acc[1] += a0.y * b;
            acc[2] += a0.z * b; acc[3] += a0.w * b;
            acc[4] += a1.x * b; acc[5] += a1.y * b;
            acc[6] += a1.z * b; acc[7] += a1.w * b;
        }
    }
    #pragma unroll
    for (int r = 0; r < 8; r++) {
        int i = i0 + ty * 8 + r;
        if (tx < 16) g_cat[(size_t)i * CATD + h * 16 + tx] = acc[r];
        else         g_opt[i * 288 + h * 24 + (tx - 16)]   = acc[r];
    }
}

// ---------- inverse frame transform + norm -> cat sections ----------------
__global__ void transform_kernel(const float* __restrict__ rot,
                                 const float* __restrict__ trans) {
    int n = blockIdx.x;
    __shared__ float R[9], t3[3];
    int tid = threadIdx.x;   // 128
    if (tid < 9) R[tid] = rot[n * 9 + tid];
    if (tid < 3) t3[tid] = trans[n * 3 + tid];
    __syncthreads();
    if (tid < 96) {
        int h = tid >> 3, p = tid & 7;
        int base = n * 288 + h * 24 + p * 3;
        float x = g_opt[base + 0] - t3[0];
        float y = g_opt[base + 1] - t3[1];
        float z = g_opt[base + 2] - t3[2];
        float lx = R[0] * x + R[3] * y + R[6] * z;
        float ly = R[1] * x + R[4] * y + R[7] * z;
        float lz = R[2] * x + R[5] * y + R[8] * z;
        size_t o = (size_t)n * CATD;
        int idx = h * 8 + p;
        g_cat[o + 192 + idx] = lx;
        g_cat[o + 288 + idx] = ly;
        g_cat[o + 384 + idx] = lz;
        g_cat[o + 480 + idx] = sqrtf(lx * lx + ly * ly + lz * lz + 1e-8f);
    }
}

// ---------- o_pair: cat[i, 576 + h*128 + c] = sum_j a[h,i,j] z[i,j,c] -----
__global__ void opair_kernel(const float* __restrict__ z) {
    int i = blockIdx.x;
    __shared__ float as[Hh][Nn];   // 24 KB
    int tid = threadIdx.x;   // 128 (= channel c)
    for (int t = tid; t < Hh * Nn; t += 128) {
        int h = t >> 9, j = t & 511;
        as[h][j] = g_att[(h << 18) + (i << 9) + j];
    }
    __syncthreads();
    float acc[Hh];
    #pragma unroll
    for (int h = 0; h < Hh; h++) acc[h] = 0.f;
    const float* zrow = z + (size_t)i * Nn * CZ + tid;
    #pragma unroll 4
    for (int j = 0; j < Nn; j++) {
        float zv = zrow[(size_t)j * CZ];
        #pragma unroll
        for (int h = 0; h < Hh; h++) acc[h] += as[h][j] * zv;
    }
    size_t o = (size_t)i * CATD + 576;
    #pragma unroll
    for (int h = 0; h < Hh; h++) g_cat[o + h * CZ + tid] = acc[h];
}

// --------------------------------------------------------------------------
extern "C" void kernel_launch(void* const* d_in, const int* in_sizes, int n_in,
                              void* d_out, int out_size) {
    const float* s      = (const float*)d_in[0];
    const float* z      = (const float*)d_in[1];
    const float* rot    = (const float*)d_in[2];
    const float* trans  = (const float*)d_in[3];
    const float* mask   = (const float*)d_in[4];
    const float* Wq     = (const float*)d_in[5];
    const float* bq     = (const float*)d_in[6];
    const float* Wkv    = (const float*)d_in[7];
    const float* bkv    = (const float*)d_in[8];
    const float* Wqp    = (const float*)d_in[9];
    const float* bqp    = (const float*)d_in[10];
    const float* Wkvp   = (const float*)d_in[11];
    const float* bkvp   = (const float*)d_in[12];
    const float* Wb     = (const float*)d_in[13];
    const float* bb     = (const float*)d_in[14];
    const float* head_w = (const float*)d_in[15];
    const float* Wout   = (const float*)d_in[16];
    const float* bout   = (const float*)d_in[17];
    float* out = (float*)d_out;

    float *p_Wcat, *p_bcat, *p_proj, *p_cat;
    cudaGetSymbolAddress((void**)&p_Wcat, g_Wcat);
    cudaGetSymbolAddress((void**)&p_bcat, g_bcat);
    cudaGetSymbolAddress((void**)&p_proj, g_proj);
    cudaGetSymbolAddress((void**)&p_cat,  g_cat);

    // pack projection weights (+ fold q scale)
    packW_kernel<<<(CS * PROJD + PROJD + 255) / 256, 256>>>(Wq, bq, Wkv, bkv, Wqp, bqp, Wkvp, bkvp);
    // fused projection GEMM: [512,1024]@[1024,1152]
    gemm128_kernel<<<dim3(PROJD / 32, Nn / 128), 128>>>(s, p_Wcat, p_bcat, p_proj, PROJD, CS);
    // rigid transforms
    pts_kernel<<<Nn, 192>>>(rot, trans);
    // pair bias (scaled)
    bias_kernel<<<NN / 8, 128>>>(z, Wb, bb);
    // attention logits + softmax
    attn_kernel<<<dim3(Hh, Nn), 256>>>(head_w, mask);
    // a@v and a@v_pts as batched GEMM
    av_kernel<<<dim3(Hh, Nn / 64), 320>>>();
    // inverse frame transform + norms
    transform_kernel<<<Nn, 128>>>(rot, trans);
    // pair output
    opair_kernel<<<Nn, 128>>>(z);
    // final projection: [512,2112]@[2112,1024]
    gemm128_kernel<<<dim3(CS / 32, Nn / 128), 128>>>(p_cat, Wout, bout, out, CS, CATD);
}

// round 3
// speedup vs baseline: 4.5896x; 1.9516x over previous
#include <cuda_runtime.h>
#include <math.h>

#define Nn 512
#define CS 1024
#define CZ 128
#define Hh 12
#define HD 16
#define PQ 4
#define PV 8
#define CATD 2112   // 192 + 96*4 + 1536
#define NN (Nn*Nn)
#define PROJD 1152  // 192 + 384 + 144 + 432
#define QS 0.14433756729740643f   // sqrt(1/48)

// ---------------- scratch (device globals; no allocation) ----------------
__device__ float g_proj[Nn*PROJD];        // [n][ q(192,scaled) | kv(384) | qp_raw(144) | kvp_raw(432) ]
__device__ float g_qpts[Nn*Hh*PQ*3];
__device__ float g_kpts[Nn*Hh*PQ*3];
__device__ float g_vpts[Nn*Hh*PV*3];
__device__ float g_bias[Hh*NN];           // [h][i][j], pre-scaled by sqrt(1/3)
__device__ float g_att[Hh*NN];
__device__ float g_opt[Nn*Hh*PV*3];
__device__ float g_cat[Nn*CATD];

// ---------------- f32x2 packed helpers ------------------------------------
__device__ __forceinline__ unsigned long long pk2(float x, float y) {
    unsigned long long r;
    asm("mov.b64 %0, {%1,%2};" : "=l"(r) : "f"(x), "f"(y));
    return r;
}
__device__ __forceinline__ unsigned long long dup2(float x) {
    unsigned long long r;
    asm("mov.b64 %0, {%1,%1};" : "=l"(r) : "f"(x));
    return r;
}
#define FMA2(c, a, b) asm("fma.rn.f32x2 %0, %1, %2, %0;" : "+l"(c) : "l"(a), "l"(b))
__device__ __forceinline__ void unpk2(unsigned long long v, float& lo, float& hi) {
    asm("mov.b64 {%0,%1}, %2;" : "=f"(lo), "=f"(hi) : "l"(v));
}

// ---------------- GEMM: C[M,Nd] = A[M,K]@W[K,Nd] + bias, f32x2 ------------
// BM=64, BN=64, BK=16, 256 threads, 4x4 micro-tile in packed pairs.
// PROJ=true: W is the 4 concatenated projection matrices; q-scale folded in.
template<bool PROJ>
__global__ void __launch_bounds__(256)
gemm64_kernel(const float* __restrict__ A,
              const float* __restrict__ W0,  const float* __restrict__ b0,
              const float* __restrict__ Wkv, const float* __restrict__ bkv,
              const float* __restrict__ Wqp, const float* __restrict__ bqp,
              const float* __restrict__ Wkvp,const float* __restrict__ bkvp,
              float* __restrict__ C, int Nd, int K) {
    __shared__ unsigned long long As2[16][64];   // [k][row] dup pairs {a,a}
    __shared__ unsigned long long Bs2[16][32];   // [k][colpair] {b0,b1}
    int tid = threadIdx.x;
    int m0 = blockIdx.y * 64, n0 = blockIdx.x * 64;
    int tx = tid & 15, ty = tid >> 4;            // compute mapping

    // A loader: row = tid>>2, k-offset = (tid&3)*4
    int arow = tid >> 2, akb = (tid & 3) * 4;
    const float* Aptr = A + (size_t)(m0 + arow) * K + akb;

    // B loader: col = n0 + tx*4, k-row = ty
    int lcol = n0 + tx * 4;
    const float* Bsrc; int ldw; int lc;
    if (PROJ) {
        if      (lcol < 192) { Bsrc = W0;   ldw = 192; lc = lcol;       }
        else if (lcol < 576) { Bsrc = Wkv;  ldw = 384; lc = lcol - 192; }
        else if (lcol < 720) { Bsrc = Wqp;  ldw = 144; lc = lcol - 576; }
        else                 { Bsrc = Wkvp; ldw = 432; lc = lcol - 720; }
    } else { Bsrc = W0; ldw = Nd; lc = lcol; }
    const float* Bptr = Bsrc + (size_t)ty * ldw + lc;

    float4 a4 = *(const float4*)Aptr;
    float4 b4 = *(const float4*)Bptr;

    unsigned long long acc[4][2];
    #pragma unroll
    for (int r = 0; r < 4; r++) { acc[r][0] = 0ull; acc[r][1] = 0ull; }

    int KT = K >> 4;
    for (int kt = 0; kt < KT; kt++) {
        __syncthreads();
        As2[akb + 0][arow] = dup2(a4.x);
        As2[akb + 1][arow] = dup2(a4.y);
        As2[akb + 2][arow] = dup2(a4.z);
        As2[akb + 3][arow] = dup2(a4.w);
        Bs2[ty][tx * 2]     = pk2(b4.x, b4.y);
        Bs2[ty][tx * 2 + 1] = pk2(b4.z, b4.w);
        __syncthreads();
        if (kt + 1 < KT) {
            a4 = *(const float4*)(Aptr + (kt + 1) * 16);
            b4 = *(const float4*)(Bptr + (size_t)(kt + 1) * 16 * ldw);
        }
        #pragma unroll
        for (int kk = 0; kk < 16; kk++) {
            ulonglong2 ap0 = *(const ulonglong2*)&As2[kk][ty * 4];
            ulonglong2 ap1 = *(const ulonglong2*)&As2[kk][ty * 4 + 2];
            ulonglong2 bp  = *(const ulonglong2*)&Bs2[kk][tx * 2];
            FMA2(acc[0][0], ap0.x, bp.x); FMA2(acc[0][1], ap0.x, bp.y);
            FMA2(acc[1][0], ap0.y, bp.x); FMA2(acc[1][1], ap0.y, bp.y);
            FMA2(acc[2][0], ap1.x, bp.x); FMA2(acc[2][1], ap1.x, bp.y);
            FMA2(acc[3][0], ap1.y, bp.x); FMA2(acc[3][1], ap1.y, bp.y);
        }
    }
    // epilogue: bias source for the compute column (same mapping as loader)
    const float* bsrc; float scale;
    if (PROJ) {
        if      (lcol < 192) { bsrc = b0;   scale = QS; }
        else if (lcol < 576) { bsrc = bkv;  scale = 1.f; }
        else if (lcol < 720) { bsrc = bqp;  scale = 1.f; }
        else                 { bsrc = bkvp; scale = 1.f; }
    } else { bsrc = b0; scale = 1.f; }
    float4 bv = *(const float4*)(bsrc + lc);
    #pragma unroll
    for (int r = 0; r < 4; r++) {
        float o0, o1, o2, o3;
        unpk2(acc[r][0], o0, o1);
        unpk2(acc[r][1], o2, o3);
        float4 o;
        o.x = (o0 + bv.x) * scale; o.y = (o1 + bv.y) * scale;
        o.z = (o2 + bv.z) * scale; o.w = (o3 + bv.w) * scale;
        *(float4*)(C + (size_t)(m0 + ty * 4 + r) * Nd + n0 + tx * 4) = o;
    }
}

// ------------- point transforms (fused q_pts + kv_pts) --------------------
__global__ void pts_kernel(const float* __restrict__ rot,
                           const float* __restrict__ trans) {
    int n = blockIdx.x;
    __shared__ float R[9], t3[3];
    int tid = threadIdx.x;   // 192
    if (tid < 9) R[tid] = rot[n * 9 + tid];
    if (tid < 3) t3[tid] = trans[n * 3 + tid];
    __syncthreads();
    if (tid < 48) {
        int idx = tid;
        const float* raw = g_proj + n * PROJD + 576;
        float p0 = raw[idx], p1 = raw[48 + idx], p2 = raw[96 + idx];
        #pragma unroll
        for (int c = 0; c < 3; c++)
            g_qpts[n * 144 + idx * 3 + c] =
                R[c * 3] * p0 + R[c * 3 + 1] * p1 + R[c * 3 + 2] * p2 + t3[c];
    } else {
        int idx = tid - 48;
        const float* raw = g_proj + n * PROJD + 720;
        float p0 = raw[idx], p1 = raw[144 + idx], p2 = raw[288 + idx];
        int h = idx / 12, r = idx - h * 12;
        float o[3];
        #pragma unroll
        for (int c = 0; c < 3; c++)
            o[c] = R[c * 3] * p0 + R[c * 3 + 1] * p1 + R[c * 3 + 2] * p2 + t3[c];
        if (r < PQ) {
            #pragma unroll
            for (int c = 0; c < 3; c++) g_kpts[n * 144 + h * 12 + r * 3 + c] = o[c];
        } else {
            int p = r - PQ;
            #pragma unroll
            for (int c = 0; c < 3; c++) g_vpts[n * 288 + h * 24 + p * 3 + c] = o[c];
        }
    }
}

// ---------- bias: b[h][ij] = sqrt(1/3)*(z[ij,:]@Wb[:,h] + bb[h]) ----------
// 128 rows/block, thread-per-row, 12 heads in registers, c processed in halves.
__global__ void __launch_bounds__(128)
bias_kernel(const float* __restrict__ z,
            const float* __restrict__ Wb,
            const float* __restrict__ bb) {
    int base = blockIdx.x * 128;   // 2048 blocks
    __shared__ float zs[128][68];      // half of channels, padded
    __shared__ float WbT[Hh][CZ];      // transposed Wb
    int tid = threadIdx.x;
    for (int t = tid; t < CZ * Hh; t += 128) {
        int c = t & 127, h = t >> 7;
        WbT[h][c] = Wb[c * Hh + h];
    }
    float acc[Hh];
    #pragma unroll
    for (int h = 0; h < Hh; h++) acc[h] = bb[h];
    #pragma unroll
    for (int half = 0; half < 2; half++) {
        __syncthreads();
        for (int t = tid; t < 2048; t += 128) {
            int row = t >> 4, cc = (t & 15) * 4;
            *(float4*)&zs[row][cc] =
                *(const float4*)&z[(size_t)(base + row) * CZ + half * 64 + cc];
        }
        __syncthreads();
        #pragma unroll
        for (int c4 = 0; c4 < 16; c4++) {
            float4 zv = *(const float4*)&zs[tid][c4 * 4];
            #pragma unroll
            for (int h = 0; h < Hh; h++) {
                float4 wv = *(const float4*)&WbT[h][half * 64 + c4 * 4];
                acc[h] += zv.x * wv.x + zv.y * wv.y + zv.z * wv.z + zv.w * wv.w;
            }
        }
    }
    int ij = base + tid;
    #pragma unroll
    for (int h = 0; h < Hh; h++)
        g_bias[h * NN + ij] = 0.5773502691896258f * acc[h];
}

// ---------- attention logits + softmax, 4 query rows per block ------------
__global__ void __launch_bounds__(256)
attn_kernel(const float* __restrict__ head_w,
            const float* __restrict__ mask) {
    int h = blockIdx.x, i0 = blockIdx.y * 4;
    __shared__ float qv[4][16], qp[4][12], s_mi4[4];
    __shared__ float red[4][8];
    __shared__ float s_hw, s_res[4];
    int tid = threadIdx.x, lane = tid & 31, wid = tid >> 5;
    if (tid < 64) {
        int ii = tid >> 4, d = tid & 15;
        qv[ii][d] = g_proj[(i0 + ii) * PROJD + h * 16 + d];   // pre-scaled q
    }
    if (tid < 48) {
        int ii = tid / 12, e = tid - ii * 12;
        qp[ii][e] = g_qpts[(i0 + ii) * 144 + h * 12 + e];
    }
    if (tid < 4) s_mi4[tid] = mask[i0 + tid];
    if (tid == 0) {
        float w = head_w[h];
        float sp = fmaxf(w, 0.f) + log1pf(__expf(-fabsf(w)));
        s_hw = sp * 0.13608276348795434f;   // sqrt(1/54)
    }
    __syncthreads();
    float logit[4][2];
    #pragma unroll
    for (int jj = 0; jj < 2; jj++) {
        int j = tid + jj * 256;
        float kx[16], kp[12];
        const float* kptr = g_proj + (size_t)j * PROJD + 192 + h * 32;
        #pragma unroll
        for (int d = 0; d < 16; d++) kx[d] = kptr[d];
        const float* kpp = g_kpts + j * 144 + h * 12;
        #pragma unroll
        for (int e = 0; e < 12; e++) kp[e] = kpp[e];
        float mj = mask[j];
        #pragma unroll
        for (int ii = 0; ii < 4; ii++) {
            float dot = 0.f;
            #pragma unroll
            for (int d = 0; d < 16; d++) dot += qv[ii][d] * kx[d];
            float pts = 0.f;
            #pragma unroll
            for (int e = 0; e < 12; e++) { float dd = qp[ii][e] - kp[e]; pts += dd * dd; }
            logit[ii][jj] = dot + g_bias[(h << 18) + ((i0 + ii) << 9) + j]
                          - 0.5f * s_hw * pts
                          + 100000.0f * (s_mi4[ii] * mj - 1.0f);
        }
    }
    // per-row max
    #pragma unroll
    for (int ii = 0; ii < 4; ii++) {
        float m = fmaxf(logit[ii][0], logit[ii][1]);
        #pragma unroll
        for (int o = 16; o > 0; o >>= 1) m = fmaxf(m, __shfl_xor_sync(0xffffffffu, m, o));
        if (lane == 0) red[ii][wid] = m;
    }
    __syncthreads();
    if (tid < 4) {
        float mm = red[tid][0];
        #pragma unroll
        for (int w = 1; w < 8; w++) mm = fmaxf(mm, red[tid][w]);
        s_res[tid] = mm;
    }
    __syncthreads();
    float e[4][2];
    #pragma unroll
    for (int ii = 0; ii < 4; ii++) {
        float m = s_res[ii];
        e[ii][0] = __expf(logit[ii][0] - m);
        e[ii][1] = __expf(logit[ii][1] - m);
        float ss = e[ii][0] + e[ii][1];
        #pragma unroll
        for (int o = 16; o > 0; o >>= 1) ss += __shfl_xor_sync(0xffffffffu, ss, o);
        if (lane == 0) red[ii][wid] = ss;
    }
    __syncthreads();
    if (tid < 4) {
        float t = 0.f;
        #pragma unroll
        for (int w = 0; w < 8; w++) t += red[tid][w];
        s_res[tid] = 1.f / t;
    }
    __syncthreads();
    #pragma unroll
    for (int ii = 0; ii < 4; ii++) {
        float inv = s_res[ii];
        int o = (h << 18) + ((i0 + ii) << 9);
        g_att[o + tid]       = e[ii][0] * inv;
        g_att[o + tid + 256] = e[ii][1] * inv;
    }
}

// ---------- a@[v | v_pts] per head, 32-row tiles --------------------------
__global__ void __launch_bounds__(320)
av_kernel() {
    int h = blockIdx.x;
    int i0 = blockIdx.y * 32;
    __shared__ float As[32][36];   // [j][ii]
    __shared__ float Vt[32][40];
    int tid = threadIdx.x;
    int tx = tid % 40, ty = tid / 40;   // ty 0..7
    float acc[4] = {};
    for (int k0 = 0; k0 < Nn; k0 += 32) {
        __syncthreads();
        for (int t = tid; t < 1024; t += 320) {
            int j = t & 31, ii = t >> 5;
            As[j][ii] = g_att[(h << 18) + ((i0 + ii) << 9) + k0 + j];
        }
        for (int t = tid; t < 1280; t += 320) {
            int col = t % 40, row = t / 40;
            Vt[row][col] = (col < 16)
                ? g_proj[(size_t)(k0 + row) * PROJD + 192 + h * 32 + 16 + col]
                : g_vpts[(k0 + row) * 288 + h * 24 + (col - 16)];
        }
        __syncthreads();
        #pragma unroll
        for (int j = 0; j < 32; j++) {
            float b = Vt[j][tx];
            float4 a = *(const float4*)&As[j][ty * 4];
            acc[0] += a.x * b; acc[1] += a.y * b;
            acc[2] += a.z * b; acc[3] += a.w * b;
        }
    }
    #pragma unroll
    for (int r = 0; r < 4; r++) {
        int i = i0 + ty * 4 + r;
        if (tx < 16) g_cat[(size_t)i * CATD + h * 16 + tx] = acc[r];
        else         g_opt[i * 288 + h * 24 + (tx - 16)]   = acc[r];
    }
}

// ---------- inverse frame transform + norm -> cat sections ----------------
__global__ void transform_kernel(const float* __restrict__ rot,
                                 const float* __restrict__ trans) {
    int n = blockIdx.x;
    __shared__ float R[9], t3[3];
    int tid = threadIdx.x;   // 128
    if (tid < 9) R[tid] = rot[n * 9 + tid];
    if (tid < 3) t3[tid] = trans[n * 3 + tid];
    __syncthreads();
    if (tid < 96) {
        int h = tid >> 3, p = tid & 7;
        int base = n * 288 + h * 24 + p * 3;
        float x = g_opt[base + 0] - t3[0];
        float y = g_opt[base + 1] - t3[1];
        float z = g_opt[base + 2] - t3[2];
        float lx = R[0] * x + R[3] * y + R[6] * z;
        float ly = R[1] * x + R[4] * y + R[7] * z;
        float lz = R[2] * x + R[5] * y + R[8] * z;
        size_t o = (size_t)n * CATD;
        int idx = h * 8 + p;
        g_cat[o + 192 + idx] = lx;
        g_cat[o + 288 + idx] = ly;
        g_cat[o + 384 + idx] = lz;
        g_cat[o + 480 + idx] = sqrtf(lx * lx + ly * ly + lz * lz + 1e-8f);
    }
}

// ---------- o_pair: 512 threads, 4 j-quarters + smem reduction ------------
__global__ void __launch_bounds__(512)
opair_kernel(const float* __restrict__ z) {
    int i = blockIdx.x;
    __shared__ float as[Hh][520];   // also reused as reduction scratch
    int tid = threadIdx.x;
    int c = tid & 127, jq = tid >> 7;
    for (int t = tid; t < Hh * Nn; t += 512) {
        int h = t >> 9, j = t & 511;
        as[h][j] = g_att[(h << 18) + (i << 9) + j];
    }
    __syncthreads();
    float acc[Hh];
    #pragma unroll
    for (int h = 0; h < Hh; h++) acc[h] = 0.f;
    const float* zrow = z + (size_t)i * Nn * CZ + c;
    int j0 = jq * 128;
    #pragma unroll 2
    for (int j = j0; j < j0 + 128; j++) {
        float zv = zrow[(size_t)j * CZ];
        #pragma unroll
        for (int h = 0; h < Hh; h++) acc[h] += as[h][j] * zv;
    }
    __syncthreads();
    float* red = &as[0][0];   // 6240 floats >= 3*12*128
    if (jq > 0) {
        #pragma unroll
        for (int h = 0; h < Hh; h++) red[(jq - 1) * 1536 + h * 128 + c] = acc[h];
    }
    __syncthreads();
    if (jq == 0) {
        size_t o = (size_t)i * CATD + 576;
        #pragma unroll
        for (int h = 0; h < Hh; h++) {
            float v = acc[h] + red[h * 128 + c] + red[1536 + h * 128 + c]
                             + red[3072 + h * 128 + c];
            g_cat[o + h * CZ + c] = v;
        }
    }
}

// --------------------------------------------------------------------------
extern "C" void kernel_launch(void* const* d_in, const int* in_sizes, int n_in,
                              void* d_out, int out_size) {
    const float* s      = (const float*)d_in[0];
    const float* z      = (const float*)d_in[1];
    const float* rot    = (const float*)d_in[2];
    const float* trans  = (const float*)d_in[3];
    const float* mask   = (const float*)d_in[4];
    const float* Wq     = (const float*)d_in[5];
    const float* bq     = (const float*)d_in[6];
    const float* Wkv    = (const float*)d_in[7];
    const float* bkv    = (const float*)d_in[8];
    const float* Wqp    = (const float*)d_in[9];
    const float* bqp    = (const float*)d_in[10];
    const float* Wkvp   = (const float*)d_in[11];
    const float* bkvp   = (const float*)d_in[12];
    const float* Wb     = (const float*)d_in[13];
    const float* bb     = (const float*)d_in[14];
    const float* head_w = (const float*)d_in[15];
    const float* Wout   = (const float*)d_in[16];
    const float* bout   = (const float*)d_in[17];
    float* out = (float*)d_out;

    float *p_proj, *p_cat;
    cudaGetSymbolAddress((void**)&p_proj, g_proj);
    cudaGetSymbolAddress((void**)&p_cat,  g_cat);

    // fused projection GEMM: [512,1024]@[1024,1152] (q-scale folded)
    gemm64_kernel<true><<<dim3(PROJD / 64, Nn / 64), 256>>>(
        s, Wq, bq, Wkv, bkv, Wqp, bqp, Wkvp, bkvp, p_proj, PROJD, CS);
    // rigid transforms
    pts_kernel<<<Nn, 192>>>(rot, trans);
    // pair bias (scaled by sqrt(1/3))
    bias_kernel<<<NN / 128, 128>>>(z, Wb, bb);
    // attention logits + softmax (4 rows/block)
    attn_kernel<<<dim3(Hh, Nn / 4), 256>>>(head_w, mask);
    // a@v and a@v_pts
    av_kernel<<<dim3(Hh, Nn / 32), 320>>>();
    // inverse frame transform + norms
    transform_kernel<<<Nn, 128>>>(rot, trans);
    // pair output
    opair_kernel<<<Nn, 512>>>(z);
    // final projection: [512,2112]@[2112,1024]
    gemm64_kernel<false><<<dim3(CS / 64, Nn / 64), 256>>>(
        p_cat, Wout, bout, 0, 0, 0, 0, 0, 0, out, CS, CATD);
}

// round 4
// speedup vs baseline: 5.0985x; 1.1109x over previous
#include <cuda_runtime.h>
#include <math.h>

#define Nn 512
#define CS 1024
#define CZ 128
#define Hh 12
#define HD 16
#define PQ 4
#define PV 8
#define CATD 2112   // 192 + 96*4 + 1536
#define NN (Nn*Nn)
#define PROJD 1152  // 192 + 384 + 144 + 432
#define QS 0.14433756729740643f   // sqrt(1/48)

// ---------------- scratch (device globals; no allocation) ----------------
__device__ float g_proj[Nn*PROJD];        // [n][ q(192,scaled) | kv(384) | qp(144) | kvp(432) ]
__device__ float g_qpts[Nn*Hh*PQ*3];      // [n][h][p][c]
__device__ float g_kT[Hh*HD*Nn];          // [h][d][j]
__device__ float g_vT[Hh*HD*Nn];          // [h][d][j]
__device__ float g_kptsT[Hh*12*Nn];       // [h][p*3+c][j]
__device__ float g_vptsT[Hh*24*Nn];       // [h][p*3+c][j]
__device__ float g_bias[Hh*NN];           // [h][i][j], pre-scaled by sqrt(1/3)
__device__ float g_att[Hh*NN];
__device__ float g_opt[Nn*Hh*PV*3];
__device__ float g_cat[Nn*CATD];

// ---------------- f32x2 packed helpers ------------------------------------
__device__ __forceinline__ unsigned long long pk2(float x, float y) {
    unsigned long long r;
    asm("mov.b64 %0, {%1,%2};" : "=l"(r) : "f"(x), "f"(y));
    return r;
}
__device__ __forceinline__ unsigned long long dup2(float x) {
    unsigned long long r;
    asm("mov.b64 %0, {%1,%1};" : "=l"(r) : "f"(x));
    return r;
}
#define FMA2(c, a, b) asm("fma.rn.f32x2 %0, %1, %2, %0;" : "+l"(c) : "l"(a), "l"(b))
__device__ __forceinline__ void unpk2(unsigned long long v, float& lo, float& hi) {
    asm("mov.b64 {%0,%1}, %2;" : "=f"(lo), "=f"(hi) : "l"(v));
}

// ---------------- GEMM: C[M,Nd] = A[M,K]@W[K,Nd] + bias, f32x2 ------------
template<bool PROJ>
__global__ void __launch_bounds__(256)
gemm64_kernel(const float* __restrict__ A,
              const float* __restrict__ W0,  const float* __restrict__ b0,
              const float* __restrict__ Wkv, const float* __restrict__ bkv,
              const float* __restrict__ Wqp, const float* __restrict__ bqp,
              const float* __restrict__ Wkvp,const float* __restrict__ bkvp,
              float* __restrict__ C, int Nd, int K) {
    __shared__ unsigned long long As2[16][64];   // [k][row] dup pairs {a,a}
    __shared__ unsigned long long Bs2[16][32];   // [k][colpair] {b0,b1}
    int tid = threadIdx.x;
    int m0 = blockIdx.y * 64, n0 = blockIdx.x * 64;
    int tx = tid & 15, ty = tid >> 4;

    int arow = tid >> 2, akb = (tid & 3) * 4;
    const float* Aptr = A + (size_t)(m0 + arow) * K + akb;

    int lcol = n0 + tx * 4;
    const float* Bsrc; int ldw; int lc;
    if (PROJ) {
        if      (lcol < 192) { Bsrc = W0;   ldw = 192; lc = lcol;       }
        else if (lcol < 576) { Bsrc = Wkv;  ldw = 384; lc = lcol - 192; }
        else if (lcol < 720) { Bsrc = Wqp;  ldw = 144; lc = lcol - 576; }
        else                 { Bsrc = Wkvp; ldw = 432; lc = lcol - 720; }
    } else { Bsrc = W0; ldw = Nd; lc = lcol; }
    const float* Bptr = Bsrc + (size_t)ty * ldw + lc;

    float4 a4 = *(const float4*)Aptr;
    float4 b4 = *(const float4*)Bptr;

    unsigned long long acc[4][2];
    #pragma unroll
    for (int r = 0; r < 4; r++) { acc[r][0] = 0ull; acc[r][1] = 0ull; }

    int KT = K >> 4;
    for (int kt = 0; kt < KT; kt++) {
        __syncthreads();
        As2[akb + 0][arow] = dup2(a4.x);
        As2[akb + 1][arow] = dup2(a4.y);
        As2[akb + 2][arow] = dup2(a4.z);
        As2[akb + 3][arow] = dup2(a4.w);
        Bs2[ty][tx * 2]     = pk2(b4.x, b4.y);
        Bs2[ty][tx * 2 + 1] = pk2(b4.z, b4.w);
        __syncthreads();
        if (kt + 1 < KT) {
            a4 = *(const float4*)(Aptr + (kt + 1) * 16);
            b4 = *(const float4*)(Bptr + (size_t)(kt + 1) * 16 * ldw);
        }
        #pragma unroll
        for (int kk = 0; kk < 16; kk++) {
            ulonglong2 ap0 = *(const ulonglong2*)&As2[kk][ty * 4];
            ulonglong2 ap1 = *(const ulonglong2*)&As2[kk][ty * 4 + 2];
            ulonglong2 bp  = *(const ulonglong2*)&Bs2[kk][tx * 2];
            FMA2(acc[0][0], ap0.x, bp.x); FMA2(acc[0][1], ap0.x, bp.y);
            FMA2(acc[1][0], ap0.y, bp.x); FMA2(acc[1][1], ap0.y, bp.y);
            FMA2(acc[2][0], ap1.x, bp.x); FMA2(acc[2][1], ap1.x, bp.y);
            FMA2(acc[3][0], ap1.y, bp.x); FMA2(acc[3][1], ap1.y, bp.y);
        }
    }
    const float* bsrc; float scale;
    if (PROJ) {
        if      (lcol < 192) { bsrc = b0;   scale = QS; }
        else if (lcol < 576) { bsrc = bkv;  scale = 1.f; }
        else if (lcol < 720) { bsrc = bqp;  scale = 1.f; }
        else                 { bsrc = bkvp; scale = 1.f; }
    } else { bsrc = b0; scale = 1.f; }
    float4 bv = *(const float4*)(bsrc + lc);
    #pragma unroll
    for (int r = 0; r < 4; r++) {
        float o0, o1, o2, o3;
        unpk2(acc[r][0], o0, o1);
        unpk2(acc[r][1], o2, o3);
        float4 o;
        o.x = (o0 + bv.x) * scale; o.y = (o1 + bv.y) * scale;
        o.z = (o2 + bv.z) * scale; o.w = (o3 + bv.w) * scale;
        *(float4*)(C + (size_t)(m0 + ty * 4 + r) * Nd + n0 + tx * 4) = o;
    }
}

// ------------- repack k/v into transposed [h][d][j] layouts ---------------
__global__ void repack_kv_kernel() {
    int n = blockIdx.x;
    int tid = threadIdx.x;   // 384 = h*32 + d
    float v = g_proj[n * PROJD + 192 + tid];
    int h = tid >> 5, d = tid & 31;
    if (d < 16) g_kT[(h * 16 + d) * Nn + n] = v;
    else        g_vT[(h * 16 + d - 16) * Nn + n] = v;
}

// ------------- point transforms; k/v points written transposed ------------
__global__ void pts_kernel(const float* __restrict__ rot,
                           const float* __restrict__ trans) {
    int n = blockIdx.x;
    __shared__ float R[9], t3[3];
    int tid = threadIdx.x;   // 192
    if (tid < 9) R[tid] = rot[n * 9 + tid];
    if (tid < 3) t3[tid] = trans[n * 3 + tid];
    __syncthreads();
    if (tid < 48) {
        int idx = tid;
        const float* raw = g_proj + n * PROJD + 576;
        float p0 = raw[idx], p1 = raw[48 + idx], p2 = raw[96 + idx];
        #pragma unroll
        for (int c = 0; c < 3; c++)
            g_qpts[n * 144 + idx * 3 + c] =
                R[c * 3] * p0 + R[c * 3 + 1] * p1 + R[c * 3 + 2] * p2 + t3[c];
    } else {
        int idx = tid - 48;
        const float* raw = g_proj + n * PROJD + 720;
        float p0 = raw[idx], p1 = raw[144 + idx], p2 = raw[288 + idx];
        int h = idx / 12, r = idx - h * 12;
        float o[3];
        #pragma unroll
        for (int c = 0; c < 3; c++)
            o[c] = R[c * 3] * p0 + R[c * 3 + 1] * p1 + R[c * 3 + 2] * p2 + t3[c];
        if (r < PQ) {
            #pragma unroll
            for (int c = 0; c < 3; c++)
                g_kptsT[(h * 12 + r * 3 + c) * Nn + n] = o[c];
        } else {
            int p = r - PQ;
            #pragma unroll
            for (int c = 0; c < 3; c++)
                g_vptsT[(h * 24 + p * 3 + c) * Nn + n] = o[c];
        }
    }
}

// ---------- bias: b[h][ij] = sqrt(1/3)*(z[ij,:]@Wb[:,h] + bb[h]) ----------
__global__ void __launch_bounds__(128)
bias_kernel(const float* __restrict__ z,
            const float* __restrict__ Wb,
            const float* __restrict__ bb) {
    int base = blockIdx.x * 128;
    __shared__ float zs[128][68];
    __shared__ float WbT[Hh][CZ];
    int tid = threadIdx.x;
    for (int t = tid; t < CZ * Hh; t += 128) {
        int c = t & 127, h = t >> 7;
        WbT[h][c] = Wb[c * Hh + h];
    }
    float acc[Hh];
    #pragma unroll
    for (int h = 0; h < Hh; h++) acc[h] = bb[h];
    #pragma unroll
    for (int half = 0; half < 2; half++) {
        __syncthreads();
        for (int t = tid; t < 2048; t += 128) {
            int row = t >> 4, cc = (t & 15) * 4;
            *(float4*)&zs[row][cc] =
                *(const float4*)&z[(size_t)(base + row) * CZ + half * 64 + cc];
        }
        __syncthreads();
        #pragma unroll
        for (int c4 = 0; c4 < 16; c4++) {
            float4 zv = *(const float4*)&zs[tid][c4 * 4];
            #pragma unroll
            for (int h = 0; h < Hh; h++) {
                float4 wv = *(const float4*)&WbT[h][half * 64 + c4 * 4];
                acc[h] += zv.x * wv.x + zv.y * wv.y + zv.z * wv.z + zv.w * wv.w;
            }
        }
    }
    int ij = base + tid;
    #pragma unroll
    for (int h = 0; h < Hh; h++)
        g_bias[h * NN + ij] = 0.5773502691896258f * acc[h];
}

// ---------- attention logits + softmax, 8 query rows per block ------------
__global__ void __launch_bounds__(256)
attn_kernel(const float* __restrict__ head_w,
            const float* __restrict__ mask) {
    int h = blockIdx.x, i0 = blockIdx.y * 8;
    __shared__ float qv[8][16], qp[8][12], mi8[8];
    __shared__ float red[8][8];
    __shared__ float s_hw, s_res[8];
    int tid = threadIdx.x, lane = tid & 31, wid = tid >> 5;
    if (tid < 128) {
        int ii = tid >> 4, d = tid & 15;
        qv[ii][d] = g_proj[(i0 + ii) * PROJD + h * 16 + d];
    }
    if (tid < 96) {
        int ii = tid / 12, e = tid - ii * 12;
        qp[ii][e] = g_qpts[(i0 + ii) * 144 + h * 12 + e];
    }
    if (tid < 8) mi8[tid] = mask[i0 + tid];
    if (tid == 0) {
        float w = head_w[h];
        float sp = fmaxf(w, 0.f) + log1pf(__expf(-fabsf(w)));
        s_hw = sp * 0.5f * 0.13608276348795434f;   // 0.5*sqrt(1/54)
    }
    __syncthreads();
    float logit[8][2];
    #pragma unroll
    for (int jj = 0; jj < 2; jj++) {
        int j = tid + jj * 256;
        float kx[16], kp[12];
        #pragma unroll
        for (int d = 0; d < 16; d++) kx[d] = g_kT[(h * 16 + d) * Nn + j];   // coalesced
        #pragma unroll
        for (int e = 0; e < 12; e++) kp[e] = g_kptsT[(h * 12 + e) * Nn + j];
        float mj = mask[j];
        #pragma unroll
        for (int ii = 0; ii < 8; ii++) {
            float dot = 0.f;
            #pragma unroll
            for (int d = 0; d < 16; d++) dot += qv[ii][d] * kx[d];
            float pts = 0.f;
            #pragma unroll
            for (int e = 0; e < 12; e++) { float dd = qp[ii][e] - kp[e]; pts += dd * dd; }
            logit[ii][jj] = dot + g_bias[(h << 18) + ((i0 + ii) << 9) + j]
                          - s_hw * pts
                          + 100000.0f * (mi8[ii] * mj - 1.0f);
        }
    }
    #pragma unroll
    for (int ii = 0; ii < 8; ii++) {
        float m = fmaxf(logit[ii][0], logit[ii][1]);
        #pragma unroll
        for (int o = 16; o > 0; o >>= 1) m = fmaxf(m, __shfl_xor_sync(0xffffffffu, m, o));
        if (lane == 0) red[ii][wid] = m;
    }
    __syncthreads();
    if (tid < 8) {
        float mm = red[tid][0];
        #pragma unroll
        for (int w = 1; w < 8; w++) mm = fmaxf(mm, red[tid][w]);
        s_res[tid] = mm;
    }
    __syncthreads();
    #pragma unroll
    for (int ii = 0; ii < 8; ii++) {
        float m = s_res[ii];
        logit[ii][0] = __expf(logit[ii][0] - m);
        logit[ii][1] = __expf(logit[ii][1] - m);
        float ss = logit[ii][0] + logit[ii][1];
        #pragma unroll
        for (int o = 16; o > 0; o >>= 1) ss += __shfl_xor_sync(0xffffffffu, ss, o);
        if (lane == 0) red[ii][wid] = ss;
    }
    __syncthreads();
    if (tid < 8) {
        float t = 0.f;
        #pragma unroll
        for (int w = 0; w < 8; w++) t += red[tid][w];
        s_res[tid] = 1.f / t;
    }
    __syncthreads();
    #pragma unroll
    for (int ii = 0; ii < 8; ii++) {
        float inv = s_res[ii];
        int o = (h << 18) + ((i0 + ii) << 9);
        g_att[o + tid]       = logit[ii][0] * inv;
        g_att[o + tid + 256] = logit[ii][1] * inv;
    }
}

// ---------- a@[v | v_pts] per head, 32-row tiles, coalesced loads ---------
__global__ void __launch_bounds__(320)
av_kernel() {
    int h = blockIdx.x;
    int i0 = blockIdx.y * 32;
    __shared__ float As[32][36];   // [j][ii]
    __shared__ float Vt[32][40];   // [j][col]
    int tid = threadIdx.x;
    int tx = tid % 40, ty = tid / 40;
    float acc[4] = {};
    for (int k0 = 0; k0 < Nn; k0 += 32) {
        __syncthreads();
        for (int t = tid; t < 1024; t += 320) {
            int j = t & 31, ii = t >> 5;
            As[j][ii] = g_att[(h << 18) + ((i0 + ii) << 9) + k0 + j];
        }
        for (int t = tid; t < 1280; t += 320) {
            int col = t >> 5, row = t & 31;   // row fastest => coalesced j
            Vt[row][col] = (col < 16)
                ? g_vT[(h * 16 + col) * Nn + k0 + row]
                : g_vptsT[(h * 24 + col - 16) * Nn + k0 + row];
        }
        __syncthreads();
        #pragma unroll
        for (int j = 0; j < 32; j++) {
            float b = Vt[j][tx];
            float4 a = *(const float4*)&As[j][ty * 4];
            acc[0] += a.x * b; acc[1] += a.y * b;
            acc[2] += a.z * b; acc[3] += a.w * b;
        }
    }
    #pragma unroll
    for (int r = 0; r < 4; r++) {
        int i = i0 + ty * 4 + r;
        if (tx < 16) g_cat[(size_t)i * CATD + h * 16 + tx] = acc[r];
        else         g_opt[i * 288 + h * 24 + (tx - 16)]   = acc[r];
    }
}

// ---------- inverse frame transform + norm -> cat sections ----------------
__global__ void transform_kernel(const float* __restrict__ rot,
                                 const float* __restrict__ trans) {
    int n = blockIdx.x;
    __shared__ float R[9], t3[3];
    int tid = threadIdx.x;   // 128
    if (tid < 9) R[tid] = rot[n * 9 + tid];
    if (tid < 3) t3[tid] = trans[n * 3 + tid];
    __syncthreads();
    if (tid < 96) {
        int h = tid >> 3, p = tid & 7;
        int base = n * 288 + h * 24 + p * 3;
        float x = g_opt[base + 0] - t3[0];
        float y = g_opt[base + 1] - t3[1];
        float z = g_opt[base + 2] - t3[2];
        float lx = R[0] * x + R[3] * y + R[6] * z;
        float ly = R[1] * x + R[4] * y + R[7] * z;
        float lz = R[2] * x + R[5] * y + R[8] * z;
        size_t o = (size_t)n * CATD;
        int idx = h * 8 + p;
        g_cat[o + 192 + idx] = lx;
        g_cat[o + 288 + idx] = ly;
        g_cat[o + 384 + idx] = lz;
        g_cat[o + 480 + idx] = sqrtf(lx * lx + ly * ly + lz * lz + 1e-8f);
    }
}

// ---------- o_pair: 512 threads, 4 j-quarters, MLP-4 z loads --------------
__global__ void __launch_bounds__(512)
opair_kernel(const float* __restrict__ z) {
    int i = blockIdx.x;
    __shared__ float as[Hh][520];
    int tid = threadIdx.x;
    int c = tid & 127, jq = tid >> 7;
    for (int t = tid; t < Hh * Nn; t += 512) {
        int h = t >> 9, j = t & 511;
        as[h][j] = g_att[(h << 18) + (i << 9) + j];
    }
    __syncthreads();
    float acc[Hh];
    #pragma unroll
    for (int h = 0; h < Hh; h++) acc[h] = 0.f;
    const float* zrow = z + (size_t)i * Nn * CZ + c;
    int j0 = jq * 128;
    for (int j = j0; j < j0 + 128; j += 4) {
        float z0 = zrow[(size_t)(j + 0) * CZ];
        float z1 = zrow[(size_t)(j + 1) * CZ];
        float z2 = zrow[(size_t)(j + 2) * CZ];
        float z3 = zrow[(size_t)(j + 3) * CZ];
        #pragma unroll
        for (int h = 0; h < Hh; h++)
            acc[h] += as[h][j] * z0 + as[h][j + 1] * z1
                    + as[h][j + 2] * z2 + as[h][j + 3] * z3;
    }
    __syncthreads();
    float* red = &as[0][0];
    if (jq > 0) {
        #pragma unroll
        for (int h = 0; h < Hh; h++) red[(jq - 1) * 1536 + h * 128 + c] = acc[h];
    }
    __syncthreads();
    if (jq == 0) {
        size_t o = (size_t)i * CATD + 576;
        #pragma unroll
        for (int h = 0; h < Hh; h++) {
            float v = acc[h] + red[h * 128 + c] + red[1536 + h * 128 + c]
                             + red[3072 + h * 128 + c];
            g_cat[o + h * CZ + c] = v;
        }
    }
}

// --------------------------------------------------------------------------
extern "C" void kernel_launch(void* const* d_in, const int* in_sizes, int n_in,
                              void* d_out, int out_size) {
    const float* s      = (const float*)d_in[0];
    const float* z      = (const float*)d_in[1];
    const float* rot    = (const float*)d_in[2];
    const float* trans  = (const float*)d_in[3];
    const float* mask   = (const float*)d_in[4];
    const float* Wq     = (const float*)d_in[5];
    const float* bq     = (const float*)d_in[6];
    const float* Wkv    = (const float*)d_in[7];
    const float* bkv    = (const float*)d_in[8];
    const float* Wqp    = (const float*)d_in[9];
    const float* bqp    = (const float*)d_in[10];
    const float* Wkvp   = (const float*)d_in[11];
    const float* bkvp   = (const float*)d_in[12];
    const float* Wb     = (const float*)d_in[13];
    const float* bb     = (const float*)d_in[14];
    const float* head_w = (const float*)d_in[15];
    const float* Wout   = (const float*)d_in[16];
    const float* bout   = (const float*)d_in[17];
    float* out = (float*)d_out;

    float *p_proj, *p_cat;
    cudaGetSymbolAddress((void**)&p_proj, g_proj);
    cudaGetSymbolAddress((void**)&p_cat,  g_cat);

    gemm64_kernel<true><<<dim3(PROJD / 64, Nn / 64), 256>>>(
        s, Wq, bq, Wkv, bkv, Wqp, bqp, Wkvp, bkvp, p_proj, PROJD, CS);
    repack_kv_kernel<<<Nn, 384>>>();
    pts_kernel<<<Nn, 192>>>(rot, trans);
    bias_kernel<<<NN / 128, 128>>>(z, Wb, bb);
    attn_kernel<<<dim3(Hh, Nn / 8), 256>>>(head_w, mask);
    av_kernel<<<dim3(Hh, Nn / 32), 320>>>();
    transform_kernel<<<Nn, 128>>>(rot, trans);
    opair_kernel<<<Nn, 512>>>(z);
    gemm64_kernel<false><<<dim3(CS / 64, Nn / 64), 256>>>(
        p_cat, Wout, bout, 0, 0, 0, 0, 0, 0, out, CS, CATD);
}